// round 9
// baseline (speedup 1.0000x reference)
#include <cuda_runtime.h>
#include <cstdint>

// Fixed shapes: B=8, H=W=512
#define BB 8
#define NN (512*512)          // 262144 pixels per row
#define PP (BB*NN)
#define THREADS 256
#define CTILE 2048            // px per block, k_compute
#define CBLKX (NN/CTILE)      // 128
#define RTILE 4096            // px per block, k_refine
#define RBLKX (NN/RTILE)      // 64
#define STILE 4096            // px per block, k_sum
#define SBLKX (NN/STILE)      // 64
#define NB 2048               // sample-hist bins (11-bit digit1)
#define SH1 21                // digit1 = key >> 21
#define MARGIN 2000           // sample-rank margin (~22 sigma)
#define H2CAP 65536           // refine fine-hist bins per row
#define EQCAP 2048

// ---------------- device scratch (zero-initialized at load; every kernel
// restores the all-zero invariant on what it consumes) ----------------
__device__ uint32_t g_keys[PP];        // 8 MB
__device__ uint32_t g_pl3[PP];         // 8 MB  loss3, target in sign bit
__device__ uint32_t g_hist[BB*NB];     // sample hist, zero-invariant
__device__ uint32_t g_hist2[BB*H2CAP]; // refine hist (2 MB), zero-invariant
__device__ int      g_binlo[BB];
__device__ int      g_binhi[BB];
__device__ uint32_t g_thr[BB];
__device__ int      g_shift[BB];
__device__ int      g_kneed[BB];       // remaining count within tie bin
__device__ int      g_nbelow[BB];      // zero-invariant
__device__ int      g_eqcount[BB];     // zero-invariant
__device__ uint32_t g_eqkey[BB*EQCAP];
__device__ uint32_t g_eqidx[BB*EQCAP];
__device__ int      g_done1[BB];       // zero-invariant tickets
__device__ int      g_done2[BB];
__device__ int      g_done3[BB];
__device__ int      g_rows_done;
__device__ double   g_sum_l3;          // zero-invariant
__device__ unsigned long long g_sum_tsel;
__device__ unsigned long long g_ttotal;

__device__ __forceinline__ uint32_t f2mono(float f) {
    uint32_t u = __float_as_uint(f);
    return (u & 0x80000000u) ? ~u : (u | 0x80000000u);
}

// Robust scalar read (f32 vs f64 sniff; true values are in (0,1)).
__device__ __forceinline__ double read_scalar(const void* p) {
    float f = *(const float*)p;
    if (f > 1e-6f && f < 1.0f) return (double)f;
    return *(const double*)p;
}

// 2-class log-softmax: 3 MUFU ops.
__device__ __forceinline__ void sm2(float x0, float x1,
                                    float& lp0, float& lp1, float& p0, float& p1) {
    float d = x0 - x1;
    float t = __expf(fminf(-d, 80.0f));
    p0 = __fdividef(1.0f, 1.0f + t);
    p1 = t * p0;
    lp0 = __logf(p0);
    lp1 = lp0 - d;
}

__device__ __forceinline__ void pixel_loss(float a1, float c1, float a2, float c2,
                                           float a3, float c3, int t,
                                           float kdw, float w,
                                           float& loss, float& l3) {
    float lp10, lp11, p10, p11; sm2(a1, c1, lp10, lp11, p10, p11);
    float lp20, lp21, p20, p21; sm2(a2, c2, lp20, lp21, p20, p21);
    float lp30, lp31, p30, p31; sm2(a3, c3, lp30, lp31, p30, p31);
    float tf = (float)t;
    float om11 = 1.0f - p11, om10 = 1.0f - p10;
    float om21 = 1.0f - p21, om20 = 1.0f - p20;
    float om31 = 1.0f - p31, om30 = 1.0f - p30;
    float l1 = -tf * om11*om11*lp11 - (1.0f-tf) * om10*om10*lp10;
    float l2 = -tf * om21*om21*lp21 - (1.0f-tf) * om20*om20*lp20;
    l3       = -tf * om31*om31*lp31 - (1.0f-tf) * om30*om30*lp30;
    float kdl12 = p10*(lp10-lp20) + p11*(lp11-lp21);
    float kdl21 = p20*(lp20-lp10) + p21*(lp21-lp11);
    loss = w * (l1 + l2 + l3) + kdw * (kdl12 + kdl21);
}

// ---------------- kernel 1: math + SAMPLED digit1 hist + bracket select -----
__global__ void __launch_bounds__(THREADS)
k_compute(const float* __restrict__ in1, const float* __restrict__ in2,
          const float* __restrict__ in3, const int* __restrict__ tgt,
          const void* __restrict__ kdw_p, const void* __restrict__ forget_p)
{
    __shared__ unsigned ss[256];
    __shared__ int swt[8];
    __shared__ int s_last;
    int tid = threadIdx.x;

    const int row = blockIdx.y;
    const float kdw = (float)read_scalar(kdw_p);
    const float w   = 1.0f - kdw;

    const float4* b1a = (const float4*)(in1 + (size_t)row * 2 * NN);
    const float4* b1c = (const float4*)(in1 + (size_t)row * 2 * NN + NN);
    const float4* b2a = (const float4*)(in2 + (size_t)row * 2 * NN);
    const float4* b2c = (const float4*)(in2 + (size_t)row * 2 * NN + NN);
    const float4* b3a = (const float4*)(in3 + (size_t)row * 2 * NN);
    const float4* b3c = (const float4*)(in3 + (size_t)row * 2 * NN + NN);
    const int4*   bt  = (const int4*)(tgt + (size_t)row * NN);
    uint4* kout = (uint4*)(g_keys + (size_t)row * NN);
    uint4* pout = (uint4*)(g_pl3  + (size_t)row * NN);

    int tcnt = 0;

#pragma unroll
    for (int g = 0; g < 2; g++) {
        int vi = (blockIdx.x * CTILE + g * 1024) / 4 + tid;
        float4 A1 = b1a[vi], C1 = b1c[vi];
        float4 A2 = b2a[vi], C2 = b2c[vi];
        float4 A3 = b3a[vi], C3 = b3c[vi];
        int4   T  = bt[vi];

        float ls0, ls1, ls2, ls3, l30, l31, l32, l33;
        pixel_loss(A1.x, C1.x, A2.x, C2.x, A3.x, C3.x, T.x, kdw, w, ls0, l30);
        pixel_loss(A1.y, C1.y, A2.y, C2.y, A3.y, C3.y, T.y, kdw, w, ls1, l31);
        pixel_loss(A1.z, C1.z, A2.z, C2.z, A3.z, C3.z, T.z, kdw, w, ls2, l32);
        pixel_loss(A1.w, C1.w, A2.w, C2.w, A3.w, C3.w, T.w, kdw, w, ls3, l33);

        uint4 K = make_uint4(f2mono(ls0), f2mono(ls1), f2mono(ls2), f2mono(ls3));
        kout[vi] = K;
        uint4 P = make_uint4(__float_as_uint(l30) | ((uint32_t)T.x << 31),
                             __float_as_uint(l31) | ((uint32_t)T.y << 31),
                             __float_as_uint(l32) | ((uint32_t)T.z << 31),
                             __float_as_uint(l33) | ((uint32_t)T.w << 31));
        pout[vi] = P;

        // stratified 1/8 sample: pixel index vi*4 ≡ 0 (mod 8)  ⇔  vi even
        if ((vi & 1) == 0)
            atomicAdd(&g_hist[row * NB + (K.x >> SH1)], 1u);

        tcnt += T.x + T.y + T.z + T.w;
    }

#pragma unroll
    for (int o = 16; o; o >>= 1) tcnt += __shfl_down_sync(0xffffffffu, tcnt, o);
    if ((tid & 31) == 0) swt[tid >> 5] = tcnt;
    __syncthreads();
    if (tid == 0) {
        int s = 0;
#pragma unroll
        for (int i = 0; i < 8; i++) s += swt[i];
        atomicAdd(&g_ttotal, (unsigned long long)s);
    }

    // ---- last block of this row: bracket digit1 from sample hist ----
    __threadfence();
    if (tid == 0) s_last = (atomicAdd(&g_done1[row], 1) == CBLKX - 1);
    __syncthreads();
    if (!s_last) return;
    if (tid == 0) g_done1[row] = 0;

    double rem = 1.0 - read_scalar(forget_p);
    int kneed = (int)(rem * (double)NN);
    int ks = kneed >> 3;                           // expected sample rank
    unsigned kslo = (unsigned)max(ks - MARGIN, 1);
    unsigned kshi = (unsigned)(ks + MARGIN);

    uint32_t* h = g_hist + row * NB;
    unsigned local[NB/THREADS];
    unsigned lsum = 0;
#pragma unroll
    for (int i = 0; i < NB/THREADS; i++) {
        local[i] = __ldcg(&h[tid * (NB/THREADS) + i]);
        lsum += local[i];
        h[tid * (NB/THREADS) + i] = 0u;            // restore zero-invariant
    }
    ss[tid] = lsum;
    __syncthreads();
    for (int off = 1; off < 256; off <<= 1) {
        unsigned n = (tid >= off) ? ss[tid - off] : 0u;
        __syncthreads();
        ss[tid] += n;
        __syncthreads();
    }
    unsigned incl = ss[tid];
    unsigned excl = incl - lsum;

    if (excl < kslo && kslo <= incl) {
        unsigned cum = excl;
#pragma unroll
        for (int i = 0; i < NB/THREADS; i++) {
            if (cum + local[i] >= kslo) { g_binlo[row] = tid * (NB/THREADS) + i; break; }
            cum += local[i];
        }
    }
    if (excl < kshi && kshi <= incl) {
        unsigned cum = excl;
#pragma unroll
        for (int i = 0; i < NB/THREADS; i++) {
            if (cum + local[i] >= kshi) { g_binhi[row] = tid * (NB/THREADS) + i; break; }
            cum += local[i];
        }
    }
    __syncthreads();
    if (tid == 0 && ss[THREADS-1] < kshi) g_binhi[row] = NB - 1;  // bracket tail
}

// ---------------- kernel 2: exact below-count + fine window hist + select ---
__global__ void __launch_bounds__(THREADS)
k_refine(const void* __restrict__ forget_p)
{
    __shared__ unsigned ss[256];
    __shared__ int swt[8];
    __shared__ int s_last;

    int tid = threadIdx.x;
    int row = blockIdx.y;
    int binlo = g_binlo[row];
    int binhi = g_binhi[row];

    int wbinscnt = binhi - binlo + 1;
    int subbits = 8;
    while ((wbinscnt << subbits) > H2CAP) subbits--;   // subbits in [5,8]
    int shift = SH1 - subbits;
    uint32_t lobase = ((uint32_t)binlo) << subbits;
    uint32_t* h2 = g_hist2 + row * H2CAP;

    const uint4* keys = (const uint4*)(g_keys + (size_t)row * NN);
    int vbase = blockIdx.x * (RTILE/4) + tid;

    // front-batch keys (MLP=4)
    uint4 K[4];
#pragma unroll
    for (int it = 0; it < 4; it++) K[it] = keys[vbase + it*THREADS];

    int nb = 0;
#pragma unroll
    for (int it = 0; it < 4; it++) {
        uint32_t ks4[4] = {K[it].x, K[it].y, K[it].z, K[it].w};
#pragma unroll
        for (int j = 0; j < 4; j++) {
            int d1 = (int)(ks4[j] >> SH1);
            if (d1 < binlo) nb++;
            else if (d1 <= binhi)
                atomicAdd(&h2[(ks4[j] >> shift) - lobase], 1u);
        }
    }
#pragma unroll
    for (int o = 16; o; o >>= 1) nb += __shfl_down_sync(0xffffffffu, nb, o);
    if ((tid & 31) == 0) swt[tid >> 5] = nb;
    __syncthreads();
    if (tid == 0) {
        int s = 0;
#pragma unroll
        for (int i = 0; i < 8; i++) s += swt[i];
        atomicAdd(&g_nbelow[row], s);
    }

    // ---- last block of this row: exact select within window ----
    __threadfence();
    if (tid == 0) s_last = (atomicAdd(&g_done2[row], 1) == RBLKX - 1);
    __syncthreads();
    if (!s_last) return;

    int N = __ldcg(&g_nbelow[row]);
    if (tid == 0) { g_done2[row] = 0; g_nbelow[row] = 0; }

    double rem = 1.0 - read_scalar(forget_p);
    int kneed = (int)(rem * (double)NN);
    unsigned kneed2 = (unsigned)(kneed - N);        // rank within the window

    int wbins = wbinscnt << subbits;
    int chunk = (wbins + THREADS - 1) / THREADS;
    int c0 = tid * chunk;
    int c1 = min(c0 + chunk, wbins);

    unsigned lsum = 0;
    for (int i = c0; i < c1; i++) lsum += __ldcg(&h2[i]);
    ss[tid] = lsum;
    __syncthreads();
    for (int off = 1; off < 256; off <<= 1) {
        unsigned n = (tid >= off) ? ss[tid - off] : 0u;
        __syncthreads();
        ss[tid] += n;
        __syncthreads();
    }
    unsigned incl = ss[tid];
    unsigned excl = incl - lsum;
    if (excl < kneed2 && kneed2 <= incl) {
        unsigned cum = excl;
        for (int i = c0; i < c1; i++) {
            unsigned v = __ldcg(&h2[i]);
            if (cum + v >= kneed2) {
                g_thr[row]   = (lobase + (uint32_t)i) << shift;
                g_shift[row] = shift;
                g_kneed[row] = (int)(kneed2 - cum);
                break;
            }
            cum += v;
        }
    }
    // safety clamp for (astronomically unlikely) bracket miss
    if (tid == 0 && ss[THREADS-1] < kneed2) {
        g_thr[row]   = (lobase + (uint32_t)wbins) << shift;
        g_shift[row] = shift;
        g_kneed[row] = 0;
    }
    // restore zero-invariant on the window
    for (int i = c0; i < c1; i++) h2[i] = 0u;
}

// ---------------- kernel 3: threshold sum + tie resolve + output ------------
__global__ void __launch_bounds__(THREADS)
k_sum(const void* __restrict__ forget_p, float* __restrict__ out)
{
    __shared__ double sd[8];
    __shared__ int    si[8];
    __shared__ uint32_t tkey[EQCAP];
    __shared__ uint32_t tidx[EQCAP];
    __shared__ int s_last;

    int tid = threadIdx.x;
    int row = blockIdx.y;
    uint32_t thr = g_thr[row];
    int shift = g_shift[row];
    uint32_t pfx = thr >> shift;
    const uint4* keys = (const uint4*)(g_keys + (size_t)row * NN);
    const uint4* pl3  = (const uint4*)(g_pl3  + (size_t)row * NN);

    double sld = 0.0;
    int    st = 0;

#pragma unroll
    for (int it = 0; it < STILE/(THREADS*4); it++) {
        int vi = blockIdx.x * (STILE/4) + it * THREADS + tid;
        uint4 K = keys[vi];
        uint4 P = pl3[vi];
        uint32_t ks4[4] = {K.x, K.y, K.z, K.w};
        uint32_t ps4[4] = {P.x, P.y, P.z, P.w};
        float sl = 0.0f;
#pragma unroll
        for (int j = 0; j < 4; j++) {
            if (ks4[j] < thr) {
                sl += __uint_as_float(ps4[j] & 0x7fffffffu);
                st += (int)(ps4[j] >> 31);
            } else if ((ks4[j] >> shift) == pfx) {   // tie bin
                int p = atomicAdd(&g_eqcount[row], 1);
                if (p < EQCAP) {
                    g_eqkey[row * EQCAP + p] = ks4[j];
                    g_eqidx[row * EQCAP + p] = (uint32_t)(vi * 4 + j);
                }
            }
        }
        sld += (double)sl;
    }
#pragma unroll
    for (int o = 16; o; o >>= 1) {
        sld += __shfl_down_sync(0xffffffffu, sld, o);
        st  += __shfl_down_sync(0xffffffffu, st, o);
    }
    if ((tid & 31) == 0) { sd[tid >> 5] = sld; si[tid >> 5] = st; }
    __syncthreads();
    if (tid == 0) {
        double S = 0.0; int Ti = 0;
#pragma unroll
        for (int i = 0; i < 8; i++) { S += sd[i]; Ti += si[i]; }
        atomicAdd(&g_sum_l3, S);
        atomicAdd(&g_sum_tsel, (unsigned long long)Ti);
    }

    // ---- last block of this row: resolve ties, maybe write outputs ----
    __threadfence();
    if (tid == 0) s_last = (atomicAdd(&g_done3[row], 1) == SBLKX - 1);
    __syncthreads();
    if (!s_last) return;

    int c = min(__ldcg(&g_eqcount[row]), EQCAP);
    if (tid == 0) { g_done3[row] = 0; g_eqcount[row] = 0; }
    int kneed3 = g_kneed[row];

    for (int i = tid; i < c; i += THREADS) {
        tkey[i] = __ldcg(&g_eqkey[row * EQCAP + i]);
        tidx[i] = __ldcg(&g_eqidx[row * EQCAP + i]);
    }
    __syncthreads();

    // exact rank-select by (key, idx) — stable-argsort equivalent
    double sl2 = 0.0;
    int    st2 = 0;
    for (int j = tid; j < c; j += THREADS) {
        uint32_t kj = tkey[j], ij = tidx[j];
        int rank = 0;
        for (int q = 0; q < c; q++) {
            uint32_t kq = tkey[q], iq = tidx[q];
            rank += (kq < kj || (kq == kj && iq < ij)) ? 1 : 0;
        }
        if (rank < kneed3) {
            uint32_t p = __ldcg(&g_pl3[(size_t)row * NN + ij]);
            sl2 += (double)__uint_as_float(p & 0x7fffffffu);
            st2 += (int)(p >> 31);
        }
    }
#pragma unroll
    for (int o = 16; o; o >>= 1) {
        sl2 += __shfl_down_sync(0xffffffffu, sl2, o);
        st2 += __shfl_down_sync(0xffffffffu, st2, o);
    }
    if ((tid & 31) == 0) { sd[tid >> 5] = sl2; si[tid >> 5] = st2; }
    __syncthreads();
    if (tid != 0) return;

    double S = 0.0; int Ti = 0;
#pragma unroll
    for (int i = 0; i < 8; i++) { S += sd[i]; Ti += si[i]; }
    atomicAdd(&g_sum_l3, S);
    atomicAdd(&g_sum_tsel, (unsigned long long)Ti);

    __threadfence();
    if (atomicAdd(&g_rows_done, 1) == BB - 1) {
        double sl = atomicAdd(&g_sum_l3, 0.0);
        unsigned long long ts = atomicAdd(&g_sum_tsel, 0ull);
        unsigned long long tt = atomicAdd(&g_ttotal, 0ull);
        double rem = 1.0 - read_scalar(forget_p);
        long long num_rem = (long long)(rem * (double)NN);
        double denom = (double)BB * (double)num_rem;
        out[0] = (float)(sl / denom);
        out[1] = (float)((double)ts / (double)tt);
        // restore zero-invariant for graph replays
        g_rows_done = 0;
        g_sum_l3    = 0.0;
        g_sum_tsel  = 0ull;
        g_ttotal    = 0ull;
    }
}

// ---------------- host entry ----------------
extern "C" void kernel_launch(void* const* d_in, const int* in_sizes, int n_in,
                              void* d_out, int out_size) {
    const float* in1    = (const float*)d_in[0];
    const float* in2    = (const float*)d_in[1];
    const float* in3    = (const float*)d_in[2];
    const int*   tgt    = (const int*)d_in[3];
    const void*  forget = d_in[4];
    const void*  kdw    = d_in[5];
    float* out = (float*)d_out;

    k_compute<<<dim3(CBLKX, BB), THREADS>>>(in1, in2, in3, tgt, kdw, forget);
    k_refine<<<dim3(RBLKX, BB), THREADS>>>(forget);
    k_sum<<<dim3(SBLKX, BB), THREADS>>>(forget, out);

    (void)in_sizes; (void)n_in; (void)out_size;
}

// round 10
// speedup vs baseline: 1.1039x; 1.1039x over previous
#include <cuda_runtime.h>
#include <cstdint>

// Fixed shapes: B=8, H=W=512
#define BB 8
#define NN (512*512)          // 262144 pixels per row
#define PP (BB*NN)
#define THREADS 256
#define CTILE 2048            // px per block, k_compute
#define CBLKX (NN/CTILE)      // 128
#define STILE 4096            // px per block, k_agg
#define SBLKX (NN/STILE)      // 64
#define NB 2048               // 11-bit digit bins
#define SH1 21                // digit1 = key >> 21           (11 bits)
#define SH2 10                // digit2 = (key >> 10) & 2047  (11 bits)

// ---------------- device scratch (zero-initialized at load; every kernel
// restores the all-zero invariant on what it consumes) ----------------
__device__ uint32_t g_keys[PP];       // 8 MB
__device__ uint32_t g_pl3[PP];        // 8 MB  loss3, target in sign bit
__device__ uint32_t g_hist[BB*NB];    // digit1 hist, zero-invariant
__device__ uint32_t g_cnt2[BB*NB];    // per-digit2 aggregates, zero-invariant
__device__ float    g_sl2[BB*NB];
__device__ uint32_t g_st2[BB*NB];
__device__ uint32_t g_sel1[BB];
__device__ int      g_kneed[BB];      // remaining rank within digit1 bin
__device__ int      g_done1[BB];      // zero-invariant tickets
__device__ int      g_done2[BB];
__device__ int      g_rows_done;
__device__ double   g_sum_l3;         // zero-invariant
__device__ double   g_sum_t;
__device__ unsigned long long g_ttotal;

__device__ __forceinline__ uint32_t f2mono(float f) {
    uint32_t u = __float_as_uint(f);
    return (u & 0x80000000u) ? ~u : (u | 0x80000000u);
}

// Robust scalar read (f32 vs f64 sniff; true values are in (0,1)).
__device__ __forceinline__ double read_scalar(const void* p) {
    float f = *(const float*)p;
    if (f > 1e-6f && f < 1.0f) return (double)f;
    return *(const double*)p;
}

// 2-class log-softmax: 3 MUFU ops.
__device__ __forceinline__ void sm2(float x0, float x1,
                                    float& lp0, float& lp1, float& p0, float& p1) {
    float d = x0 - x1;
    float t = __expf(fminf(-d, 80.0f));
    p0 = __fdividef(1.0f, 1.0f + t);
    p1 = t * p0;
    lp0 = __logf(p0);
    lp1 = lp0 - d;
}

__device__ __forceinline__ void pixel_loss(float a1, float c1, float a2, float c2,
                                           float a3, float c3, int t,
                                           float kdw, float w,
                                           float& loss, float& l3) {
    float lp10, lp11, p10, p11; sm2(a1, c1, lp10, lp11, p10, p11);
    float lp20, lp21, p20, p21; sm2(a2, c2, lp20, lp21, p20, p21);
    float lp30, lp31, p30, p31; sm2(a3, c3, lp30, lp31, p30, p31);
    float tf = (float)t;
    float om11 = 1.0f - p11, om10 = 1.0f - p10;
    float om21 = 1.0f - p21, om20 = 1.0f - p20;
    float om31 = 1.0f - p31, om30 = 1.0f - p30;
    float l1 = -tf * om11*om11*lp11 - (1.0f-tf) * om10*om10*lp10;
    float l2 = -tf * om21*om21*lp21 - (1.0f-tf) * om20*om20*lp20;
    l3       = -tf * om31*om31*lp31 - (1.0f-tf) * om30*om30*lp30;
    float kdl12 = p10*(lp10-lp20) + p11*(lp11-lp21);
    float kdl21 = p20*(lp20-lp10) + p21*(lp21-lp11);
    loss = w * (l1 + l2 + l3) + kdw * (kdl12 + kdl21);
}

// ---------------- kernel 1: math + digit1 smem hist + fused select ----------
__global__ void __launch_bounds__(THREADS)
k_compute(const float* __restrict__ in1, const float* __restrict__ in2,
          const float* __restrict__ in3, const int* __restrict__ tgt,
          const void* __restrict__ kdw_p, const void* __restrict__ forget_p)
{
    __shared__ uint32_t sh[NB];
    __shared__ unsigned ss[256];
    __shared__ int swt[8];
    __shared__ int s_last;
    int tid = threadIdx.x;
#pragma unroll
    for (int i = 0; i < NB/THREADS; i++) sh[tid + i*THREADS] = 0u;
    __syncthreads();

    const int row = blockIdx.y;
    const float kdw = (float)read_scalar(kdw_p);
    const float w   = 1.0f - kdw;

    const float4* b1a = (const float4*)(in1 + (size_t)row * 2 * NN);
    const float4* b1c = (const float4*)(in1 + (size_t)row * 2 * NN + NN);
    const float4* b2a = (const float4*)(in2 + (size_t)row * 2 * NN);
    const float4* b2c = (const float4*)(in2 + (size_t)row * 2 * NN + NN);
    const float4* b3a = (const float4*)(in3 + (size_t)row * 2 * NN);
    const float4* b3c = (const float4*)(in3 + (size_t)row * 2 * NN + NN);
    const int4*   bt  = (const int4*)(tgt + (size_t)row * NN);
    uint4* kout = (uint4*)(g_keys + (size_t)row * NN);
    uint4* pout = (uint4*)(g_pl3  + (size_t)row * NN);

    int tcnt = 0;

#pragma unroll
    for (int g = 0; g < 2; g++) {
        int vi = (blockIdx.x * CTILE + g * 1024) / 4 + tid;
        float4 A1 = b1a[vi], C1 = b1c[vi];
        float4 A2 = b2a[vi], C2 = b2c[vi];
        float4 A3 = b3a[vi], C3 = b3c[vi];
        int4   T  = bt[vi];

        float ls0, ls1, ls2, ls3, l30, l31, l32, l33;
        pixel_loss(A1.x, C1.x, A2.x, C2.x, A3.x, C3.x, T.x, kdw, w, ls0, l30);
        pixel_loss(A1.y, C1.y, A2.y, C2.y, A3.y, C3.y, T.y, kdw, w, ls1, l31);
        pixel_loss(A1.z, C1.z, A2.z, C2.z, A3.z, C3.z, T.z, kdw, w, ls2, l32);
        pixel_loss(A1.w, C1.w, A2.w, C2.w, A3.w, C3.w, T.w, kdw, w, ls3, l33);

        uint4 K = make_uint4(f2mono(ls0), f2mono(ls1), f2mono(ls2), f2mono(ls3));
        kout[vi] = K;
        uint4 P = make_uint4(__float_as_uint(l30) | ((uint32_t)T.x << 31),
                             __float_as_uint(l31) | ((uint32_t)T.y << 31),
                             __float_as_uint(l32) | ((uint32_t)T.z << 31),
                             __float_as_uint(l33) | ((uint32_t)T.w << 31));
        pout[vi] = P;

        atomicAdd(&sh[K.x >> SH1], 1u);
        atomicAdd(&sh[K.y >> SH1], 1u);
        atomicAdd(&sh[K.z >> SH1], 1u);
        atomicAdd(&sh[K.w >> SH1], 1u);
        tcnt += T.x + T.y + T.z + T.w;
    }
    __syncthreads();
#pragma unroll
    for (int i = 0; i < NB/THREADS; i++) {
        uint32_t v = sh[tid + i*THREADS];
        if (v) atomicAdd(&g_hist[row * NB + tid + i*THREADS], v);
    }

#pragma unroll
    for (int o = 16; o; o >>= 1) tcnt += __shfl_down_sync(0xffffffffu, tcnt, o);
    if ((tid & 31) == 0) swt[tid >> 5] = tcnt;
    __syncthreads();
    if (tid == 0) {
        int s = 0;
#pragma unroll
        for (int i = 0; i < 8; i++) s += swt[i];
        atomicAdd(&g_ttotal, (unsigned long long)s);
    }

    // ---- last block of this row: select digit1, zero hist, reset ticket ----
    __threadfence();
    if (tid == 0) s_last = (atomicAdd(&g_done1[row], 1) == CBLKX - 1);
    __syncthreads();
    if (!s_last) return;
    if (tid == 0) g_done1[row] = 0;

    double rem = 1.0 - read_scalar(forget_p);
    unsigned kneed = (unsigned)(rem * (double)NN);

    uint32_t* h = g_hist + row * NB;
    unsigned local[NB/THREADS];
    unsigned lsum = 0;
#pragma unroll
    for (int i = 0; i < NB/THREADS; i++) {
        local[i] = __ldcg(&h[tid * (NB/THREADS) + i]);
        lsum += local[i];
        h[tid * (NB/THREADS) + i] = 0u;       // restore zero-invariant
    }
    ss[tid] = lsum;
    __syncthreads();
    for (int off = 1; off < 256; off <<= 1) {
        unsigned n = (tid >= off) ? ss[tid - off] : 0u;
        __syncthreads();
        ss[tid] += n;
        __syncthreads();
    }
    unsigned incl = ss[tid];
    unsigned excl = incl - lsum;
    if (excl < kneed && kneed <= incl) {
        unsigned cum = excl;
#pragma unroll
        for (int i = 0; i < NB/THREADS; i++) {
            if (cum + local[i] >= kneed) {
                g_sel1[row]  = (uint32_t)(tid * (NB/THREADS) + i);
                g_kneed[row] = (int)(kneed - cum);
                break;
            }
            cum += local[i];
        }
    }
}

// ---------------- kernel 2: below-sum + per-digit2 aggregates + finish ------
__global__ void __launch_bounds__(THREADS)
k_agg(const void* __restrict__ forget_p, float* __restrict__ out)
{
    __shared__ unsigned ss[256];
    __shared__ double sd[8];
    __shared__ double sdt[8];
    __shared__ int s_last, s_sel2, s_kneed3;

    int tid = threadIdx.x;
    int row = blockIdx.y;
    uint32_t sel1 = g_sel1[row];
    const uint4* keys = (const uint4*)(g_keys + (size_t)row * NN);
    const uint4* pl3  = (const uint4*)(g_pl3  + (size_t)row * NN);
    uint32_t* cnt2 = g_cnt2 + row * NB;
    float*    sl2  = g_sl2  + row * NB;
    uint32_t* st2  = g_st2  + row * NB;

    double sld = 0.0;
    int    st = 0;

#pragma unroll
    for (int it = 0; it < STILE/(THREADS*4); it++) {
        int vi = blockIdx.x * (STILE/4) + it * THREADS + tid;
        uint4 K = keys[vi];
        uint4 P = pl3[vi];
        uint32_t ks4[4] = {K.x, K.y, K.z, K.w};
        uint32_t ps4[4] = {P.x, P.y, P.z, P.w};
        float sl = 0.0f;
#pragma unroll
        for (int j = 0; j < 4; j++) {
            uint32_t d1 = ks4[j] >> SH1;
            float l3v = __uint_as_float(ps4[j] & 0x7fffffffu);
            int   tv  = (int)(ps4[j] >> 31);
            if (d1 < sel1) {
                sl += l3v;
                st += tv;
            } else if (d1 == sel1) {
                uint32_t d2 = (ks4[j] >> SH2) & (NB-1);
                atomicAdd(&cnt2[d2], 1u);
                atomicAdd(&sl2[d2], l3v);
                if (tv) atomicAdd(&st2[d2], 1u);
            }
        }
        sld += (double)sl;
    }
#pragma unroll
    for (int o = 16; o; o >>= 1) {
        sld += __shfl_down_sync(0xffffffffu, sld, o);
        st  += __shfl_down_sync(0xffffffffu, st, o);
    }
    if ((tid & 31) == 0) { sd[tid >> 5] = sld; sdt[tid >> 5] = (double)st; }
    __syncthreads();
    if (tid == 0) {
        double S = 0.0, T = 0.0;
#pragma unroll
        for (int i = 0; i < 8; i++) { S += sd[i]; T += sdt[i]; }
        atomicAdd(&g_sum_l3, S);
        atomicAdd(&g_sum_t, T);
    }

    // ---- last block of this row: digit2 select + aggregate finish ----
    __threadfence();
    if (tid == 0) s_last = (atomicAdd(&g_done2[row], 1) == SBLKX - 1);
    __syncthreads();
    if (!s_last) return;
    if (tid == 0) { g_done2[row] = 0; s_sel2 = NB; s_kneed3 = 0; }

    unsigned kneed1 = (unsigned)g_kneed[row];

    // load this thread's 8 bins of aggregates
    unsigned lc[NB/THREADS];
    float    lf[NB/THREADS];
    unsigned lt[NB/THREADS];
    unsigned lsum = 0;
#pragma unroll
    for (int i = 0; i < NB/THREADS; i++) {
        int b = tid * (NB/THREADS) + i;
        lc[i] = __ldcg(&cnt2[b]);
        lf[i] = __ldcg(&sl2[b]);
        lt[i] = __ldcg(&st2[b]);
        lsum += lc[i];
        // restore zero-invariant
        cnt2[b] = 0u;  sl2[b] = 0.0f;  st2[b] = 0u;
    }
    ss[tid] = lsum;
    __syncthreads();
    for (int off = 1; off < 256; off <<= 1) {
        unsigned n = (tid >= off) ? ss[tid - off] : 0u;
        __syncthreads();
        ss[tid] += n;
        __syncthreads();
    }
    unsigned incl = ss[tid];
    unsigned excl = incl - lsum;
    if (excl < kneed1 && kneed1 <= incl) {
        unsigned cum = excl;
#pragma unroll
        for (int i = 0; i < NB/THREADS; i++) {
            if (cum + lc[i] >= kneed1) {
                s_sel2   = tid * (NB/THREADS) + i;
                s_kneed3 = (int)(kneed1 - cum);
                break;
            }
            cum += lc[i];
        }
    }
    __syncthreads();
    int sel2   = s_sel2;
    int kneed3 = s_kneed3;

    // sum aggregates for bins strictly below sel2; pro-rate the tie bin
    double dl = 0.0, dt = 0.0;
#pragma unroll
    for (int i = 0; i < NB/THREADS; i++) {
        int b = tid * (NB/THREADS) + i;
        if (b < sel2) { dl += (double)lf[i]; dt += (double)lt[i]; }
        else if (b == sel2 && lc[i] > 0) {
            double frac = (double)kneed3 / (double)lc[i];
            dl += (double)lf[i] * frac;
            dt += (double)lt[i] * frac;
        }
    }
#pragma unroll
    for (int o = 16; o; o >>= 1) {
        dl += __shfl_down_sync(0xffffffffu, dl, o);
        dt += __shfl_down_sync(0xffffffffu, dt, o);
    }
    if ((tid & 31) == 0) { sd[tid >> 5] = dl; sdt[tid >> 5] = dt; }
    __syncthreads();
    if (tid != 0) return;

    double S = 0.0, T = 0.0;
#pragma unroll
    for (int i = 0; i < 8; i++) { S += sd[i]; T += sdt[i]; }
    atomicAdd(&g_sum_l3, S);
    atomicAdd(&g_sum_t, T);

    __threadfence();
    if (atomicAdd(&g_rows_done, 1) == BB - 1) {
        double sl = atomicAdd(&g_sum_l3, 0.0);
        double ts = atomicAdd(&g_sum_t, 0.0);
        unsigned long long tt = atomicAdd(&g_ttotal, 0ull);
        double rem = 1.0 - read_scalar(forget_p);
        long long num_rem = (long long)(rem * (double)NN);
        double denom = (double)BB * (double)num_rem;
        out[0] = (float)(sl / denom);
        out[1] = (float)(ts / (double)tt);
        // restore zero-invariant for graph replays
        g_rows_done = 0;
        g_sum_l3    = 0.0;
        g_sum_t     = 0.0;
        g_ttotal    = 0ull;
    }
}

// ---------------- host entry ----------------
extern "C" void kernel_launch(void* const* d_in, const int* in_sizes, int n_in,
                              void* d_out, int out_size) {
    const float* in1    = (const float*)d_in[0];
    const float* in2    = (const float*)d_in[1];
    const float* in3    = (const float*)d_in[2];
    const int*   tgt    = (const int*)d_in[3];
    const void*  forget = d_in[4];
    const void*  kdw    = d_in[5];
    float* out = (float*)d_out;

    k_compute<<<dim3(CBLKX, BB), THREADS>>>(in1, in2, in3, tgt, kdw, forget);
    k_agg<<<dim3(SBLKX, BB), THREADS>>>(forget, out);

    (void)in_sizes; (void)n_in; (void)out_size;
}

// round 11
// speedup vs baseline: 1.4081x; 1.2756x over previous
#include <cuda_runtime.h>
#include <cstdint>

// Fixed shapes: B=8, H=W=512
#define BB 8
#define NN (512*512)          // 262144 pixels per row
#define PP (BB*NN)
#define THREADS 256
#define CTILE 2048            // px per block, k_compute
#define CBLKX (NN/CTILE)      // 128
#define STILE 4096            // px per block, k_hist / k_sum
#define SBLKX (NN/STILE)      // 64
#define NB 2048               // 11-bit digit bins
#define SH1 21                // digit1 = key >> 21           (11 bits)
#define SH2 10                // digit2 = (key >> 10) & 2047  (11 bits)
#define EQCAP 2048

// ---------------- device scratch (zero-initialized at load; every kernel
// restores the all-zero invariant on what it consumes) ----------------
__device__ uint32_t g_keys[PP];       // 8 MB
__device__ uint32_t g_pl3[PP];        // 8 MB  loss3, target in sign bit
__device__ uint32_t g_hist[BB*NB];    // zero-invariant
__device__ uint32_t g_sel1[BB];
__device__ uint32_t g_thr[BB];
__device__ int      g_kneed[BB];
__device__ int      g_eqcount[BB];    // zero-invariant
__device__ uint32_t g_eqkey[BB*EQCAP];
__device__ uint32_t g_eqidx[BB*EQCAP];
__device__ int      g_done1[BB];      // zero-invariant tickets
__device__ int      g_done2[BB];
__device__ int      g_done3[BB];
__device__ int      g_rows_done;
__device__ double   g_sum_l3;         // zero-invariant
__device__ unsigned long long g_sum_tsel;
__device__ unsigned long long g_ttotal;

__device__ __forceinline__ uint32_t f2mono(float f) {
    uint32_t u = __float_as_uint(f);
    return (u & 0x80000000u) ? ~u : (u | 0x80000000u);
}

// Robust scalar read (f32 vs f64 sniff; true values are in (0,1)).
__device__ __forceinline__ double read_scalar(const void* p) {
    float f = *(const float*)p;
    if (f > 1e-6f && f < 1.0f) return (double)f;
    return *(const double*)p;
}

// 2-class softmax primitives: p0, p1, lp0=log p0, d = x0-x1.  (3 MUFU)
__device__ __forceinline__ void sm2f(float x0, float x1,
                                     float& p0, float& p1, float& lp0, float& d) {
    d = x0 - x1;
    float t = __expf(fminf(-d, 80.0f));
    p0 = __fdividef(1.0f, 1.0f + t);
    p1 = t * p0;
    lp0 = __logf(p0);
}

// focal term via identities: 1-p1=p0, 1-p0=p1, lp1=lp0-d:
//   l = -lp0*(t*p0^2 + (1-t)*p1^2) + t*p0^2*d
__device__ __forceinline__ float focal(float tf, float p0, float p1, float lp0, float d) {
    float a = p0 * p0, b = p1 * p1;
    float c = fmaf(tf, a - b, b);            // t*a + (1-t)*b
    return fmaf(tf * a, d, -lp0 * c);
}

__device__ __forceinline__ void pixel_loss(float a1, float c1, float a2, float c2,
                                           float a3, float c3, int t,
                                           float kdw, float w,
                                           float& loss, float& l3) {
    float p10, p11, lp10, d1; sm2f(a1, c1, p10, p11, lp10, d1);
    float p20, p21, lp20, d2; sm2f(a2, c2, p20, p21, lp20, d2);
    float p30, p31, lp30, d3; sm2f(a3, c3, p30, p31, lp30, d3);
    float tf = (float)t;
    float l1 = focal(tf, p10, p11, lp10, d1);
    float l2 = focal(tf, p20, p21, lp20, d2);
    l3       = focal(tf, p30, p31, lp30, d3);
    // kdl12 + kdl21 == (p10 - p20) * (d1 - d2)   [exact identity]
    float kdl = (p10 - p20) * (d1 - d2);
    loss = w * (l1 + l2 + l3) + kdw * kdl;
}

// ---------------- kernel 1: math + digit1 smem hist + fused select ----------
__global__ void __launch_bounds__(THREADS)
k_compute(const float* __restrict__ in1, const float* __restrict__ in2,
          const float* __restrict__ in3, const int* __restrict__ tgt,
          const void* __restrict__ kdw_p, const void* __restrict__ forget_p)
{
    __shared__ uint32_t sh[NB];
    __shared__ unsigned ss[256];
    __shared__ int swt[8];
    __shared__ int s_last;
    int tid = threadIdx.x;
#pragma unroll
    for (int i = 0; i < NB/THREADS; i++) sh[tid + i*THREADS] = 0u;
    __syncthreads();

    const int row = blockIdx.y;
    const float kdw = (float)read_scalar(kdw_p);
    const float w   = 1.0f - kdw;

    const float4* b1a = (const float4*)(in1 + (size_t)row * 2 * NN);
    const float4* b1c = (const float4*)(in1 + (size_t)row * 2 * NN + NN);
    const float4* b2a = (const float4*)(in2 + (size_t)row * 2 * NN);
    const float4* b2c = (const float4*)(in2 + (size_t)row * 2 * NN + NN);
    const float4* b3a = (const float4*)(in3 + (size_t)row * 2 * NN);
    const float4* b3c = (const float4*)(in3 + (size_t)row * 2 * NN + NN);
    const int4*   bt  = (const int4*)(tgt + (size_t)row * NN);
    uint4* kout = (uint4*)(g_keys + (size_t)row * NN);
    uint4* pout = (uint4*)(g_pl3  + (size_t)row * NN);

    int tcnt = 0;

#pragma unroll
    for (int g = 0; g < 2; g++) {
        int vi = (blockIdx.x * CTILE + g * 1024) / 4 + tid;
        float4 A1 = b1a[vi], C1 = b1c[vi];
        float4 A2 = b2a[vi], C2 = b2c[vi];
        float4 A3 = b3a[vi], C3 = b3c[vi];
        int4   T  = bt[vi];

        float ls0, ls1, ls2, ls3, l30, l31, l32, l33;
        pixel_loss(A1.x, C1.x, A2.x, C2.x, A3.x, C3.x, T.x, kdw, w, ls0, l30);
        pixel_loss(A1.y, C1.y, A2.y, C2.y, A3.y, C3.y, T.y, kdw, w, ls1, l31);
        pixel_loss(A1.z, C1.z, A2.z, C2.z, A3.z, C3.z, T.z, kdw, w, ls2, l32);
        pixel_loss(A1.w, C1.w, A2.w, C2.w, A3.w, C3.w, T.w, kdw, w, ls3, l33);

        uint4 K = make_uint4(f2mono(ls0), f2mono(ls1), f2mono(ls2), f2mono(ls3));
        kout[vi] = K;
        uint4 P = make_uint4(__float_as_uint(l30) | ((uint32_t)T.x << 31),
                             __float_as_uint(l31) | ((uint32_t)T.y << 31),
                             __float_as_uint(l32) | ((uint32_t)T.z << 31),
                             __float_as_uint(l33) | ((uint32_t)T.w << 31));
        pout[vi] = P;

        atomicAdd(&sh[K.x >> SH1], 1u);
        atomicAdd(&sh[K.y >> SH1], 1u);
        atomicAdd(&sh[K.z >> SH1], 1u);
        atomicAdd(&sh[K.w >> SH1], 1u);
        tcnt += T.x + T.y + T.z + T.w;
    }
    __syncthreads();
#pragma unroll
    for (int i = 0; i < NB/THREADS; i++) {
        uint32_t v = sh[tid + i*THREADS];
        if (v) atomicAdd(&g_hist[row * NB + tid + i*THREADS], v);
    }

#pragma unroll
    for (int o = 16; o; o >>= 1) tcnt += __shfl_down_sync(0xffffffffu, tcnt, o);
    if ((tid & 31) == 0) swt[tid >> 5] = tcnt;
    __syncthreads();
    if (tid == 0) {
        int s = 0;
#pragma unroll
        for (int i = 0; i < 8; i++) s += swt[i];
        atomicAdd(&g_ttotal, (unsigned long long)s);
    }

    // ---- last block of this row: select digit1, zero hist, reset ticket ----
    __threadfence();
    if (tid == 0) s_last = (atomicAdd(&g_done1[row], 1) == CBLKX - 1);
    __syncthreads();
    if (!s_last) return;
    if (tid == 0) g_done1[row] = 0;

    double rem = 1.0 - read_scalar(forget_p);
    unsigned kneed = (unsigned)(rem * (double)NN);

    uint32_t* h = g_hist + row * NB;
    unsigned local[NB/THREADS];
    unsigned lsum = 0;
#pragma unroll
    for (int i = 0; i < NB/THREADS; i++) {
        local[i] = __ldcg(&h[tid * (NB/THREADS) + i]);
        lsum += local[i];
        h[tid * (NB/THREADS) + i] = 0u;       // restore zero-invariant
    }
    ss[tid] = lsum;
    __syncthreads();
    for (int off = 1; off < 256; off <<= 1) {
        unsigned n = (tid >= off) ? ss[tid - off] : 0u;
        __syncthreads();
        ss[tid] += n;
        __syncthreads();
    }
    unsigned incl = ss[tid];
    unsigned excl = incl - lsum;
    if (excl < kneed && kneed <= incl) {
        unsigned cum = excl;
#pragma unroll
        for (int i = 0; i < NB/THREADS; i++) {
            if (cum + local[i] >= kneed) {
                g_sel1[row]  = (uint32_t)(tid * (NB/THREADS) + i);
                g_kneed[row] = (int)(kneed - cum);
                break;
            }
            cum += local[i];
        }
    }
}

// ---------------- kernel 2: digit2 hist (front-batched keys) + select -------
__global__ void __launch_bounds__(THREADS)
k_hist()
{
    __shared__ unsigned ss[256];
    __shared__ int s_last;
    int tid = threadIdx.x;
    int row = blockIdx.y;
    uint32_t sel1 = g_sel1[row];
    const uint4* keys = (const uint4*)(g_keys + (size_t)row * NN);
    int vbase = blockIdx.x * (STILE/4) + tid;

    // front-batch all key loads (MLP=4, 16 regs)
    uint4 K0 = keys[vbase];
    uint4 K1 = keys[vbase + THREADS];
    uint4 K2 = keys[vbase + 2*THREADS];
    uint4 K3 = keys[vbase + 3*THREADS];

    uint32_t ks[16] = {K0.x,K0.y,K0.z,K0.w, K1.x,K1.y,K1.z,K1.w,
                       K2.x,K2.y,K2.z,K2.w, K3.x,K3.y,K3.z,K3.w};
#pragma unroll
    for (int j = 0; j < 16; j++)
        if ((ks[j] >> SH1) == sel1)
            atomicAdd(&g_hist[row * NB + ((ks[j] >> SH2) & (NB-1))], 1u);

    // ---- last block of this row: select digit2, zero hist, reset ticket ----
    __threadfence();
    if (tid == 0) s_last = (atomicAdd(&g_done2[row], 1) == SBLKX - 1);
    __syncthreads();
    if (!s_last) return;
    if (tid == 0) g_done2[row] = 0;

    unsigned kneed1 = (unsigned)g_kneed[row];
    uint32_t* h = g_hist + row * NB;
    unsigned local[NB/THREADS];
    unsigned lsum = 0;
#pragma unroll
    for (int i = 0; i < NB/THREADS; i++) {
        local[i] = __ldcg(&h[tid * (NB/THREADS) + i]);
        lsum += local[i];
        h[tid * (NB/THREADS) + i] = 0u;       // restore zero-invariant
    }
    ss[tid] = lsum;
    __syncthreads();
    for (int off = 1; off < 256; off <<= 1) {
        unsigned n = (tid >= off) ? ss[tid - off] : 0u;
        __syncthreads();
        ss[tid] += n;
        __syncthreads();
    }
    unsigned incl = ss[tid];
    unsigned excl = incl - lsum;
    if (excl < kneed1 && kneed1 <= incl) {
        unsigned cum = excl;
#pragma unroll
        for (int i = 0; i < NB/THREADS; i++) {
            if (cum + local[i] >= kneed1) {
                uint32_t sel2 = (uint32_t)(tid * (NB/THREADS) + i);
                g_thr[row]   = ((sel1 << 11) | sel2) << SH2;
                g_kneed[row] = (int)(kneed1 - cum);
                break;
            }
            cum += local[i];
        }
    }
}

// ---------------- kernel 3: threshold sum (batched) + ties + output ---------
__global__ void __launch_bounds__(THREADS)
k_sum(const void* __restrict__ forget_p, float* __restrict__ out)
{
    __shared__ double sd[8];
    __shared__ int    si[8];
    __shared__ uint32_t tkey[EQCAP];
    __shared__ uint32_t tidx[EQCAP];
    __shared__ int s_last;

    int tid = threadIdx.x;
    int row = blockIdx.y;
    uint32_t thr = g_thr[row];
    uint32_t pfx22 = thr >> SH2;
    const uint4* keys = (const uint4*)(g_keys + (size_t)row * NN);
    const uint4* pl3  = (const uint4*)(g_pl3  + (size_t)row * NN);
    int vbase = blockIdx.x * (STILE/4) + tid;

    // front-batch keys and payloads (MLP=8)
    uint4 K[4], P[4];
#pragma unroll
    for (int it = 0; it < 4; it++) K[it] = keys[vbase + it*THREADS];
#pragma unroll
    for (int it = 0; it < 4; it++) P[it] = pl3[vbase + it*THREADS];

    double sld = 0.0;
    int    st = 0;

#pragma unroll
    for (int it = 0; it < 4; it++) {
        uint32_t ks4[4] = {K[it].x, K[it].y, K[it].z, K[it].w};
        uint32_t ps4[4] = {P[it].x, P[it].y, P[it].z, P[it].w};
        float sl = 0.0f;
#pragma unroll
        for (int j = 0; j < 4; j++) {
            if (ks4[j] < thr) {
                sl += __uint_as_float(ps4[j] & 0x7fffffffu);
                st += (int)(ps4[j] >> 31);
            } else if ((ks4[j] >> SH2) == pfx22) {   // tie bin (~tens per row)
                int p = atomicAdd(&g_eqcount[row], 1);
                if (p < EQCAP) {
                    g_eqkey[row * EQCAP + p] = ks4[j];
                    g_eqidx[row * EQCAP + p] = (uint32_t)((vbase + it*THREADS) * 4 + j);
                }
            }
        }
        sld += (double)sl;
    }
#pragma unroll
    for (int o = 16; o; o >>= 1) {
        sld += __shfl_down_sync(0xffffffffu, sld, o);
        st  += __shfl_down_sync(0xffffffffu, st, o);
    }
    if ((tid & 31) == 0) { sd[tid >> 5] = sld; si[tid >> 5] = st; }
    __syncthreads();
    if (tid == 0) {
        double S = 0.0; int Ti = 0;
#pragma unroll
        for (int i = 0; i < 8; i++) { S += sd[i]; Ti += si[i]; }
        atomicAdd(&g_sum_l3, S);
        atomicAdd(&g_sum_tsel, (unsigned long long)Ti);
    }

    // ---- last block of this row: resolve ties, maybe write outputs ----
    __threadfence();
    if (tid == 0) s_last = (atomicAdd(&g_done3[row], 1) == SBLKX - 1);
    __syncthreads();
    if (!s_last) return;

    int c = min(__ldcg(&g_eqcount[row]), EQCAP);
    if (tid == 0) { g_done3[row] = 0; g_eqcount[row] = 0; }  // restore invariant
    int kneed2 = g_kneed[row];

    for (int i = tid; i < c; i += THREADS) {
        tkey[i] = __ldcg(&g_eqkey[row * EQCAP + i]);
        tidx[i] = __ldcg(&g_eqidx[row * EQCAP + i]);
    }
    __syncthreads();

    // exact rank-select by (key, idx) — stable-argsort equivalent
    double sl2 = 0.0;
    int    st2 = 0;
    for (int j = tid; j < c; j += THREADS) {
        uint32_t kj = tkey[j], ij = tidx[j];
        int rank = 0;
        for (int q = 0; q < c; q++) {
            uint32_t kq = tkey[q], iq = tidx[q];
            rank += (kq < kj || (kq == kj && iq < ij)) ? 1 : 0;
        }
        if (rank < kneed2) {
            uint32_t p = __ldcg(&g_pl3[(size_t)row * NN + ij]);
            sl2 += (double)__uint_as_float(p & 0x7fffffffu);
            st2 += (int)(p >> 31);
        }
    }
#pragma unroll
    for (int o = 16; o; o >>= 1) {
        sl2 += __shfl_down_sync(0xffffffffu, sl2, o);
        st2 += __shfl_down_sync(0xffffffffu, st2, o);
    }
    if ((tid & 31) == 0) { sd[tid >> 5] = sl2; si[tid >> 5] = st2; }
    __syncthreads();
    if (tid != 0) return;

    double S = 0.0; int Ti = 0;
#pragma unroll
    for (int i = 0; i < 8; i++) { S += sd[i]; Ti += si[i]; }
    atomicAdd(&g_sum_l3, S);
    atomicAdd(&g_sum_tsel, (unsigned long long)Ti);

    __threadfence();
    if (atomicAdd(&g_rows_done, 1) == BB - 1) {
        double sl = atomicAdd(&g_sum_l3, 0.0);
        unsigned long long ts = atomicAdd(&g_sum_tsel, 0ull);
        unsigned long long tt = atomicAdd(&g_ttotal, 0ull);
        double rem = 1.0 - read_scalar(forget_p);
        long long num_rem = (long long)(rem * (double)NN);
        double denom = (double)BB * (double)num_rem;
        out[0] = (float)(sl / denom);
        out[1] = (float)((double)ts / (double)tt);
        // restore zero-invariant for graph replays
        g_rows_done = 0;
        g_sum_l3    = 0.0;
        g_sum_tsel  = 0ull;
        g_ttotal    = 0ull;
    }
}

// ---------------- host entry ----------------
extern "C" void kernel_launch(void* const* d_in, const int* in_sizes, int n_in,
                              void* d_out, int out_size) {
    const float* in1    = (const float*)d_in[0];
    const float* in2    = (const float*)d_in[1];
    const float* in3    = (const float*)d_in[2];
    const int*   tgt    = (const int*)d_in[3];
    const void*  forget = d_in[4];
    const void*  kdw    = d_in[5];
    float* out = (float*)d_out;

    k_compute<<<dim3(CBLKX, BB), THREADS>>>(in1, in2, in3, tgt, kdw, forget);
    k_hist<<<dim3(SBLKX, BB), THREADS>>>();
    k_sum<<<dim3(SBLKX, BB), THREADS>>>(forget, out);

    (void)in_sizes; (void)n_in; (void)out_size;
}

// round 12
// speedup vs baseline: 1.5491x; 1.1001x over previous
#include <cuda_runtime.h>
#include <cstdint>

// Fixed shapes: B=8, H=W=512
#define BB 8
#define NN (512*512)          // 262144 pixels per row
#define PP (BB*NN)
#define THREADS 1024          // one CTA per SM
#define CTILE 16384           // px per block (4 groups of 4 px per thread)
#define CBLKX (NN/CTILE)      // 16  -> grid 128 blocks, single wave
#define STILE 16384
#define SBLKX (NN/STILE)      // 16
#define NB 2048               // 11-bit digit bins
#define SH1 21                // digit1 = key >> 21           (11 bits)
#define SH2 10                // digit2 = (key >> 10) & 2047  (11 bits)
#define EQCAP 2048

// ---------------- device scratch (zero-initialized at load; every kernel
// restores the all-zero invariant on what it consumes) ----------------
__device__ uint32_t g_keys[PP];       // 8 MB
__device__ uint32_t g_pl3[PP];        // 8 MB  loss3, target in sign bit
__device__ uint32_t g_hist[BB*NB];    // zero-invariant
__device__ uint32_t g_sel1[BB];
__device__ uint32_t g_thr[BB];
__device__ int      g_kneed[BB];
__device__ int      g_eqcount[BB];    // zero-invariant
__device__ uint32_t g_eqkey[BB*EQCAP];
__device__ uint32_t g_eqidx[BB*EQCAP];
__device__ int      g_done1[BB];      // zero-invariant tickets
__device__ int      g_done2[BB];
__device__ int      g_done3[BB];
__device__ int      g_rows_done;
__device__ double   g_sum_l3;         // zero-invariant
__device__ unsigned long long g_sum_tsel;
__device__ unsigned long long g_ttotal;

__device__ __forceinline__ uint32_t f2mono(float f) {
    uint32_t u = __float_as_uint(f);
    return (u & 0x80000000u) ? ~u : (u | 0x80000000u);
}

// Robust scalar read (f32 vs f64 sniff; true values are in (0,1)).
__device__ __forceinline__ double read_scalar(const void* p) {
    float f = *(const float*)p;
    if (f > 1e-6f && f < 1.0f) return (double)f;
    return *(const double*)p;
}

// 2-class softmax primitives: p0, p1, lp0=log p0, d = x0-x1.  (3 MUFU)
__device__ __forceinline__ void sm2f(float x0, float x1,
                                     float& p0, float& p1, float& lp0, float& d) {
    d = x0 - x1;
    float t = __expf(fminf(-d, 80.0f));
    p0 = __fdividef(1.0f, 1.0f + t);
    p1 = t * p0;
    lp0 = __logf(p0);
}

// focal term via identities: 1-p1=p0, 1-p0=p1, lp1=lp0-d:
//   l = -lp0*(t*p0^2 + (1-t)*p1^2) + t*p0^2*d
__device__ __forceinline__ float focal(float tf, float p0, float p1, float lp0, float d) {
    float a = p0 * p0, b = p1 * p1;
    float c = fmaf(tf, a - b, b);            // t*a + (1-t)*b
    return fmaf(tf * a, d, -lp0 * c);
}

__device__ __forceinline__ void pixel_loss(float a1, float c1, float a2, float c2,
                                           float a3, float c3, int t,
                                           float kdw, float w,
                                           float& loss, float& l3) {
    float p10, p11, lp10, d1; sm2f(a1, c1, p10, p11, lp10, d1);
    float p20, p21, lp20, d2; sm2f(a2, c2, p20, p21, lp20, d2);
    float p30, p31, lp30, d3; sm2f(a3, c3, p30, p31, lp30, d3);
    float tf = (float)t;
    float l1 = focal(tf, p10, p11, lp10, d1);
    float l2 = focal(tf, p20, p21, lp20, d2);
    l3       = focal(tf, p30, p31, lp30, d3);
    // kdl12 + kdl21 == (p10 - p20) * (d1 - d2)   [exact identity]
    float kdl = (p10 - p20) * (d1 - d2);
    loss = w * (l1 + l2 + l3) + kdw * kdl;
}

// 256-thread scan + bin select over NB bins; only tid<256 hold data.
// Returns true on the selecting thread with *bin/*rem set.
__device__ __forceinline__ bool scan_select(uint32_t* h, unsigned kneed,
                                            unsigned* ss, int tid,
                                            int* bin, int* rem) {
    unsigned local[NB/256];
    unsigned lsum = 0;
    if (tid < 256) {
#pragma unroll
        for (int i = 0; i < NB/256; i++) {
            local[i] = __ldcg(&h[tid * (NB/256) + i]);
            lsum += local[i];
            h[tid * (NB/256) + i] = 0u;       // restore zero-invariant
        }
        ss[tid] = lsum;
    }
    __syncthreads();
    for (int off = 1; off < 256; off <<= 1) {
        unsigned n = (tid >= off && tid < 256) ? ss[tid - off] : 0u;
        __syncthreads();
        if (tid < 256) ss[tid] += n;
        __syncthreads();
    }
    if (tid < 256) {
        unsigned incl = ss[tid];
        unsigned excl = incl - lsum;
        if (excl < kneed && kneed <= incl) {
            unsigned cum = excl;
#pragma unroll
            for (int i = 0; i < NB/256; i++) {
                if (cum + local[i] >= kneed) {
                    *bin = tid * (NB/256) + i;
                    *rem = (int)(kneed - cum);
                    return true;
                }
                cum += local[i];
            }
        }
    }
    return false;
}

// ---------------- kernel 1: math + digit1 smem hist + fused select ----------
__global__ void __launch_bounds__(THREADS, 1)
k_compute(const float* __restrict__ in1, const float* __restrict__ in2,
          const float* __restrict__ in3, const int* __restrict__ tgt,
          const void* __restrict__ kdw_p, const void* __restrict__ forget_p)
{
    __shared__ uint32_t sh[NB];
    __shared__ unsigned ss[256];
    __shared__ int swt[32];
    __shared__ int s_last;
    int tid = threadIdx.x;
#pragma unroll
    for (int i = tid; i < NB; i += THREADS) sh[i] = 0u;
    __syncthreads();

    const int row = blockIdx.y;
    const float kdw = (float)read_scalar(kdw_p);
    const float w   = 1.0f - kdw;

    const float4* b1a = (const float4*)(in1 + (size_t)row * 2 * NN);
    const float4* b1c = (const float4*)(in1 + (size_t)row * 2 * NN + NN);
    const float4* b2a = (const float4*)(in2 + (size_t)row * 2 * NN);
    const float4* b2c = (const float4*)(in2 + (size_t)row * 2 * NN + NN);
    const float4* b3a = (const float4*)(in3 + (size_t)row * 2 * NN);
    const float4* b3c = (const float4*)(in3 + (size_t)row * 2 * NN + NN);
    const int4*   bt  = (const int4*)(tgt + (size_t)row * NN);
    uint4* kout = (uint4*)(g_keys + (size_t)row * NN);
    uint4* pout = (uint4*)(g_pl3  + (size_t)row * NN);

    int tcnt = 0;

#pragma unroll 1
    for (int g = 0; g < 4; g++) {
        int vi = (blockIdx.x * CTILE + g * (THREADS*4)) / 4 + tid;
        float4 A1 = b1a[vi], C1 = b1c[vi];
        float4 A2 = b2a[vi], C2 = b2c[vi];
        float4 A3 = b3a[vi], C3 = b3c[vi];
        int4   T  = bt[vi];

        float ls0, ls1, ls2, ls3, l30, l31, l32, l33;
        pixel_loss(A1.x, C1.x, A2.x, C2.x, A3.x, C3.x, T.x, kdw, w, ls0, l30);
        pixel_loss(A1.y, C1.y, A2.y, C2.y, A3.y, C3.y, T.y, kdw, w, ls1, l31);
        pixel_loss(A1.z, C1.z, A2.z, C2.z, A3.z, C3.z, T.z, kdw, w, ls2, l32);
        pixel_loss(A1.w, C1.w, A2.w, C2.w, A3.w, C3.w, T.w, kdw, w, ls3, l33);

        uint4 K = make_uint4(f2mono(ls0), f2mono(ls1), f2mono(ls2), f2mono(ls3));
        kout[vi] = K;
        uint4 P = make_uint4(__float_as_uint(l30) | ((uint32_t)T.x << 31),
                             __float_as_uint(l31) | ((uint32_t)T.y << 31),
                             __float_as_uint(l32) | ((uint32_t)T.z << 31),
                             __float_as_uint(l33) | ((uint32_t)T.w << 31));
        pout[vi] = P;

        atomicAdd(&sh[K.x >> SH1], 1u);
        atomicAdd(&sh[K.y >> SH1], 1u);
        atomicAdd(&sh[K.z >> SH1], 1u);
        atomicAdd(&sh[K.w >> SH1], 1u);
        tcnt += T.x + T.y + T.z + T.w;
    }
    __syncthreads();
    for (int i = tid; i < NB; i += THREADS) {
        uint32_t v = sh[i];
        if (v) atomicAdd(&g_hist[row * NB + i], v);
    }

#pragma unroll
    for (int o = 16; o; o >>= 1) tcnt += __shfl_down_sync(0xffffffffu, tcnt, o);
    if ((tid & 31) == 0) swt[tid >> 5] = tcnt;
    __syncthreads();
    if (tid == 0) {
        int s = 0;
#pragma unroll
        for (int i = 0; i < 32; i++) s += swt[i];
        atomicAdd(&g_ttotal, (unsigned long long)s);
    }

    // ---- last block of this row: select digit1, zero hist, reset ticket ----
    __threadfence();
    if (tid == 0) s_last = (atomicAdd(&g_done1[row], 1) == CBLKX - 1);
    __syncthreads();
    if (!s_last) return;
    if (tid == 0) g_done1[row] = 0;

    double rem = 1.0 - read_scalar(forget_p);
    unsigned kneed = (unsigned)(rem * (double)NN);

    int bin, remk;
    if (scan_select(g_hist + row * NB, kneed, ss, tid, &bin, &remk)) {
        g_sel1[row]  = (uint32_t)bin;
        g_kneed[row] = remk;
    }
}

// ---------------- kernel 2: digit2 hist (front-batched keys) + select -------
__global__ void __launch_bounds__(THREADS, 1)
k_hist()
{
    __shared__ unsigned ss[256];
    __shared__ int s_last;
    int tid = threadIdx.x;
    int row = blockIdx.y;
    uint32_t sel1 = g_sel1[row];
    const uint4* keys = (const uint4*)(g_keys + (size_t)row * NN);
    int vbase = blockIdx.x * (STILE/4) + tid;

    // front-batch all key loads (MLP=4, 16 regs)
    uint4 K0 = keys[vbase];
    uint4 K1 = keys[vbase + THREADS];
    uint4 K2 = keys[vbase + 2*THREADS];
    uint4 K3 = keys[vbase + 3*THREADS];

    uint32_t ks[16] = {K0.x,K0.y,K0.z,K0.w, K1.x,K1.y,K1.z,K1.w,
                       K2.x,K2.y,K2.z,K2.w, K3.x,K3.y,K3.z,K3.w};
#pragma unroll
    for (int j = 0; j < 16; j++)
        if ((ks[j] >> SH1) == sel1)
            atomicAdd(&g_hist[row * NB + ((ks[j] >> SH2) & (NB-1))], 1u);

    // ---- last block of this row: select digit2, zero hist, reset ticket ----
    __threadfence();
    if (tid == 0) s_last = (atomicAdd(&g_done2[row], 1) == SBLKX - 1);
    __syncthreads();
    if (!s_last) return;
    if (tid == 0) g_done2[row] = 0;

    unsigned kneed1 = (unsigned)g_kneed[row];
    int bin, remk;
    if (scan_select(g_hist + row * NB, kneed1, ss, tid, &bin, &remk)) {
        g_thr[row]   = ((sel1 << 11) | (uint32_t)bin) << SH2;
        g_kneed[row] = remk;
    }
}

// ---------------- kernel 3: threshold sum (batched) + ties + output ---------
__global__ void __launch_bounds__(THREADS, 1)
k_sum(const void* __restrict__ forget_p, float* __restrict__ out)
{
    __shared__ double sd[32];
    __shared__ int    si[32];
    __shared__ uint32_t tkey[EQCAP];
    __shared__ uint32_t tidx[EQCAP];
    __shared__ int s_last;

    int tid = threadIdx.x;
    int row = blockIdx.y;
    uint32_t thr = g_thr[row];
    uint32_t pfx22 = thr >> SH2;
    const uint4* keys = (const uint4*)(g_keys + (size_t)row * NN);
    const uint4* pl3  = (const uint4*)(g_pl3  + (size_t)row * NN);
    int vbase = blockIdx.x * (STILE/4) + tid;

    double sld = 0.0;
    int    st = 0;

#pragma unroll 1
    for (int it = 0; it < 4; it++) {
        uint4 K = keys[vbase + it*THREADS];
        uint4 P = pl3[vbase + it*THREADS];
        uint32_t ks4[4] = {K.x, K.y, K.z, K.w};
        uint32_t ps4[4] = {P.x, P.y, P.z, P.w};
        float sl = 0.0f;
#pragma unroll
        for (int j = 0; j < 4; j++) {
            if (ks4[j] < thr) {
                sl += __uint_as_float(ps4[j] & 0x7fffffffu);
                st += (int)(ps4[j] >> 31);
            } else if ((ks4[j] >> SH2) == pfx22) {   // tie bin (~tens per row)
                int p = atomicAdd(&g_eqcount[row], 1);
                if (p < EQCAP) {
                    g_eqkey[row * EQCAP + p] = ks4[j];
                    g_eqidx[row * EQCAP + p] = (uint32_t)((vbase + it*THREADS) * 4 + j);
                }
            }
        }
        sld += (double)sl;
    }
#pragma unroll
    for (int o = 16; o; o >>= 1) {
        sld += __shfl_down_sync(0xffffffffu, sld, o);
        st  += __shfl_down_sync(0xffffffffu, st, o);
    }
    if ((tid & 31) == 0) { sd[tid >> 5] = sld; si[tid >> 5] = st; }
    __syncthreads();
    if (tid == 0) {
        double S = 0.0; int Ti = 0;
#pragma unroll
        for (int i = 0; i < 32; i++) { S += sd[i]; Ti += si[i]; }
        atomicAdd(&g_sum_l3, S);
        atomicAdd(&g_sum_tsel, (unsigned long long)Ti);
    }

    // ---- last block of this row: resolve ties, maybe write outputs ----
    __threadfence();
    if (tid == 0) s_last = (atomicAdd(&g_done3[row], 1) == SBLKX - 1);
    __syncthreads();
    if (!s_last) return;

    int c = min(__ldcg(&g_eqcount[row]), EQCAP);
    if (tid == 0) { g_done3[row] = 0; g_eqcount[row] = 0; }  // restore invariant
    int kneed2 = g_kneed[row];

    for (int i = tid; i < c; i += THREADS) {
        tkey[i] = __ldcg(&g_eqkey[row * EQCAP + i]);
        tidx[i] = __ldcg(&g_eqidx[row * EQCAP + i]);
    }
    __syncthreads();

    // exact rank-select by (key, idx) — stable-argsort equivalent
    double sl2 = 0.0;
    int    st2 = 0;
    for (int j = tid; j < c; j += THREADS) {
        uint32_t kj = tkey[j], ij = tidx[j];
        int rank = 0;
        for (int q = 0; q < c; q++) {
            uint32_t kq = tkey[q], iq = tidx[q];
            rank += (kq < kj || (kq == kj && iq < ij)) ? 1 : 0;
        }
        if (rank < kneed2) {
            uint32_t p = __ldcg(&g_pl3[(size_t)row * NN + ij]);
            sl2 += (double)__uint_as_float(p & 0x7fffffffu);
            st2 += (int)(p >> 31);
        }
    }
#pragma unroll
    for (int o = 16; o; o >>= 1) {
        sl2 += __shfl_down_sync(0xffffffffu, sl2, o);
        st2 += __shfl_down_sync(0xffffffffu, st2, o);
    }
    if ((tid & 31) == 0) { sd[tid >> 5] = sl2; si[tid >> 5] = st2; }
    __syncthreads();
    if (tid != 0) return;

    double S = 0.0; int Ti = 0;
#pragma unroll
    for (int i = 0; i < 32; i++) { S += sd[i]; Ti += si[i]; }
    atomicAdd(&g_sum_l3, S);
    atomicAdd(&g_sum_tsel, (unsigned long long)Ti);

    __threadfence();
    if (atomicAdd(&g_rows_done, 1) == BB - 1) {
        double sl = atomicAdd(&g_sum_l3, 0.0);
        unsigned long long ts = atomicAdd(&g_sum_tsel, 0ull);
        unsigned long long tt = atomicAdd(&g_ttotal, 0ull);
        double rem = 1.0 - read_scalar(forget_p);
        long long num_rem = (long long)(rem * (double)NN);
        double denom = (double)BB * (double)num_rem;
        out[0] = (float)(sl / denom);
        out[1] = (float)((double)ts / (double)tt);
        // restore zero-invariant for graph replays
        g_rows_done = 0;
        g_sum_l3    = 0.0;
        g_sum_tsel  = 0ull;
        g_ttotal    = 0ull;
    }
}

// ---------------- host entry ----------------
extern "C" void kernel_launch(void* const* d_in, const int* in_sizes, int n_in,
                              void* d_out, int out_size) {
    const float* in1    = (const float*)d_in[0];
    const float* in2    = (const float*)d_in[1];
    const float* in3    = (const float*)d_in[2];
    const int*   tgt    = (const int*)d_in[3];
    const void*  forget = d_in[4];
    const void*  kdw    = d_in[5];
    float* out = (float*)d_out;

    k_compute<<<dim3(CBLKX, BB), THREADS>>>(in1, in2, in3, tgt, kdw, forget);
    k_hist<<<dim3(SBLKX, BB), THREADS>>>();
    k_sum<<<dim3(SBLKX, BB), THREADS>>>(forget, out);

    (void)in_sizes; (void)n_in; (void)out_size;
}